// round 1
// baseline (speedup 1.0000x reference)
#include <cuda_runtime.h>
#include <cstdint>

#define K_CODES 8192
#define CDIM    256
#define SPAT    4096
#define NROWS   32768            // 8 * 4096
#define OUT_ELEMS (8 * CDIM * SPAT)

// ---- scratch (no allocations allowed) ----
__device__ float  g_cbT[CDIM * K_CODES];   // codebook transposed [c][k], 8 MB
__device__ float  g_cbn[K_CODES];          // ||c_k||^2 (fp32)
__device__ float  g_zn[NROWS];             // ||z_n||^2 (fp32)
__device__ int    g_idx[NROWS];
__device__ double g_loss;

// ---------------- K1: codebook transpose + norms ----------------
__global__ void k_cbprep(const float* __restrict__ cb) {
    int k = blockIdx.x;
    int c = threadIdx.x;
    float v = cb[k * CDIM + c];
    g_cbT[(size_t)c * K_CODES + k] = v;
    float s = v * v;
    #pragma unroll
    for (int o = 16; o > 0; o >>= 1) s += __shfl_xor_sync(~0u, s, o);
    __shared__ float ws[8];
    if ((c & 31) == 0) ws[c >> 5] = s;
    __syncthreads();
    if (c == 0) {
        float t = 0.f;
        #pragma unroll
        for (int i = 0; i < 8; i++) t += ws[i];
        g_cbn[k] = t;
    }
}

// ---------------- K2: z row norms ----------------
__global__ void k_zn(const float* __restrict__ z) {
    int n = blockIdx.x * 256 + threadIdx.x;
    int b = n >> 12, p = n & 4095;
    const float* zp = z + (size_t)b * CDIM * SPAT + p;
    float s = 0.f;
    #pragma unroll 8
    for (int c = 0; c < CDIM; c++) {
        float v = zp[(size_t)c * SPAT];
        s = fmaf(v, v, s);
    }
    g_zn[n] = s;
}

// ---------------- K0: zero loss accumulator ----------------
__global__ void k_zero() { g_loss = 0.0; }

// ---------------- K3: distance GEMM + argmin ----------------
// grid = 256 CTAs (128 rows each), 256 threads; each CTA scans all 8192 codes.
__global__ void __launch_bounds__(256, 2)
k_argmin(const float* __restrict__ z) {
    __shared__ float As[2][8][128];
    __shared__ float Bs[2][8][128];

    int tid = threadIdx.x;
    int tx = tid & 15, ty = tid >> 4;
    int n0 = blockIdx.x * 128;
    int b = n0 >> 12, p0 = n0 & 4095;
    const float* zbase = z + (size_t)b * CDIM * SPAT + p0;

    int lci = tid >> 5;            // 0..7  (c within chunk)
    int lni = (tid & 31) << 2;     // 0..124 (n/k within tile, float4)

    float best_d[8];
    int   best_k[8];
    #pragma unroll
    for (int i = 0; i < 8; i++) { best_d[i] = 3.4e38f; best_k[i] = 0; }

    float acc[8][8];
    #pragma unroll
    for (int i = 0; i < 8; i++)
        #pragma unroll
        for (int j = 0; j < 8; j++) acc[i][j] = 0.f;

    #pragma unroll 1
    for (int kt = 0; kt < K_CODES / 128; kt++) {
        int k0 = kt * 128;

        float4 aReg = *(const float4*)(zbase + (size_t)lci * SPAT + lni);
        float4 bReg = *(const float4*)(g_cbT + (size_t)lci * K_CODES + k0 + lni);
        *(float4*)&As[0][lci][lni] = aReg;
        *(float4*)&Bs[0][lci][lni] = bReg;
        __syncthreads();

        #pragma unroll 1
        for (int cs = 0; cs < 32; cs++) {
            int cur = cs & 1;
            if (cs < 31) {
                int c0 = (cs + 1) * 8;
                aReg = *(const float4*)(zbase + (size_t)(c0 + lci) * SPAT + lni);
                bReg = *(const float4*)(g_cbT + (size_t)(c0 + lci) * K_CODES + k0 + lni);
            }
            #pragma unroll
            for (int cc = 0; cc < 8; cc++) {
                float a[8], bb[8];
                *(float4*)&a[0]  = *(float4*)&As[cur][cc][ty * 8];
                *(float4*)&a[4]  = *(float4*)&As[cur][cc][ty * 8 + 4];
                *(float4*)&bb[0] = *(float4*)&Bs[cur][cc][tx * 8];
                *(float4*)&bb[4] = *(float4*)&Bs[cur][cc][tx * 8 + 4];
                #pragma unroll
                for (int i = 0; i < 8; i++)
                    #pragma unroll
                    for (int j = 0; j < 8; j++)
                        acc[i][j] = fmaf(a[i], bb[j], acc[i][j]);
            }
            if (cs < 31) {
                int nxt = cur ^ 1;
                *(float4*)&As[nxt][lci][lni] = aReg;
                *(float4*)&Bs[nxt][lci][lni] = bReg;
            }
            __syncthreads();
        }

        // epilogue: d = fl( fl(Z + cbn_k) - fl(2*dot) ), argmin first-index
        float4 c0v = *(const float4*)(g_cbn + k0 + tx * 8);
        float4 c1v = *(const float4*)(g_cbn + k0 + tx * 8 + 4);
        float cbn8[8] = {c0v.x, c0v.y, c0v.z, c0v.w, c1v.x, c1v.y, c1v.z, c1v.w};
        #pragma unroll
        for (int i = 0; i < 8; i++) {
            float Z = g_zn[n0 + ty * 8 + i];
            #pragma unroll
            for (int j = 0; j < 8; j++) {
                float t1 = __fadd_rn(Z, cbn8[j]);
                // 2*acc is exact, so fused form == fl(t1 - fl(2*acc))
                float d = __fmaf_rn(-2.0f, acc[i][j], t1);
                if (d < best_d[i]) { best_d[i] = d; best_k[i] = k0 + tx * 8 + j; }
                acc[i][j] = 0.f;
            }
        }
    }

    // reduce across the 16 tx lanes (same rows), lower index wins ties
    #pragma unroll
    for (int i = 0; i < 8; i++) {
        float d = best_d[i];
        int   k = best_k[i];
        #pragma unroll
        for (int o = 8; o > 0; o >>= 1) {
            float od = __shfl_xor_sync(~0u, d, o, 16);
            int   ok = __shfl_xor_sync(~0u, k, o, 16);
            if (od < d || (od == d && ok < k)) { d = od; k = ok; }
        }
        if (tx == 0) g_idx[n0 + ty * 8 + i] = k;
    }
}

// ---------------- K4: gather output + loss partial ----------------
__global__ void k_out(const float* __restrict__ z, const float* __restrict__ cb,
                      float* __restrict__ out, int out_size) {
    int n = blockIdx.x * 256 + threadIdx.x;
    int b = n >> 12, p = n & 4095;
    int myk = g_idx[n];
    const float* crow = cb + (size_t)myk * CDIM;
    const float* zp = z + (size_t)b * CDIM * SPAT + p;
    float* op = out + (size_t)b * CDIM * SPAT + p;
    double ls = 0.0;
    #pragma unroll 4
    for (int c = 0; c < CDIM; c++) {
        float q  = crow[c];
        float zv = zp[(size_t)c * SPAT];
        op[(size_t)c * SPAT] = q;           // z_q_st == z_q numerically
        float dlt = q - zv;
        ls += (double)dlt * (double)dlt;
    }
    #pragma unroll
    for (int o = 16; o > 0; o >>= 1) ls += __shfl_xor_sync(~0u, ls, o);
    __shared__ double ws[8];
    if ((threadIdx.x & 31) == 0) ws[threadIdx.x >> 5] = ls;
    __syncthreads();
    if (threadIdx.x == 0) {
        double t = 0.0;
        #pragma unroll
        for (int i = 0; i < 8; i++) t += ws[i];
        atomicAdd(&g_loss, t);
    }
    if (out_size >= OUT_ELEMS + 1 + NROWS)
        out[OUT_ELEMS + 1 + n] = (float)myk;
}

// ---------------- K5: finalize loss ----------------
__global__ void k_fin(float* __restrict__ out, int out_size) {
    if (out_size >= OUT_ELEMS + 1)
        out[OUT_ELEMS] = (float)((2.0 * g_loss) / (double)OUT_ELEMS);
}

extern "C" void kernel_launch(void* const* d_in, const int* in_sizes, int n_in,
                              void* d_out, int out_size) {
    const float* z  = (const float*)d_in[0];
    const float* cb = (const float*)d_in[1];
    if (n_in >= 2 && in_sizes[0] == K_CODES * CDIM) {  // tolerate swapped order
        z  = (const float*)d_in[1];
        cb = (const float*)d_in[0];
    }
    float* out = (float*)d_out;

    k_cbprep<<<K_CODES, 256>>>(cb);
    k_zn<<<NROWS / 256, 256>>>(z);
    k_zero<<<1, 1>>>();
    k_argmin<<<NROWS / 128, 256>>>(z);
    k_out<<<NROWS / 256, 256>>>(z, cb, out, out_size);
    k_fin<<<1, 1>>>(out, out_size);
}